// round 14
// baseline (speedup 1.0000x reference)
#include <cuda_runtime.h>
#include <cuda_bf16.h>
#include <math.h>
#include <stdint.h>

#define Bn 4
#define Nn 6400
#define Dn 32
#define Gn 20
#define NCH 50            // Nn / 128 chunks
#define MARGINf 0.3f
#define EPSf 1e-12f
#define MT 128            // anchors per block (4 warps x 2 x m16)
#define NT 128            // candidate tile rows
#define NSPLIT 9
#define BSTRIDE 208       // smem bytes per candidate row (192B data + 16B pad)
#define SMEM_NEG (NT * BSTRIDE)

// ---------------- scratch (device globals) ----------------
// ext rows (K=96): A = [hi|hi|lo] (12 uint4), B = [hi|lo|hi] (12 uint4).
// dot = hi*hi + hi*lo + lo*hi  (lo*lo dropped, ~2e-5 abs err on unit vectors)
__device__ float    g_mcoeff[Bn * Nn * Dn];  // compacted fp32 coeffs (for pos_d)
__device__ uint4    g_ea4[Bn * Nn * 12];     // anchor-ext rows
__device__ uint4    g_eb4[Bn * Nn * 12];     // cand-ext rows
__device__ unsigned char g_mgrp[Bn * Nn];    // compact slot -> group id
__device__ int      g_slot[Bn * Nn];         // original j -> compact slot
__device__ float    g_negS[NSPLIT][Bn * Nn]; // per-split max sim over different-group fg
__device__ int      g_ccnt[Bn][NCH][Gn];
__device__ int      g_cbase[Bn][NCH][Gn];
__device__ int      g_cnt[Bn][Gn];
__device__ int      g_offs[Bn][Gn + 1];
__device__ double   g_sum;
__device__ int      g_num;
__device__ int      g_done;
__device__ int      g_arrive;   // k_prep arrival counter (reset by k_loss finalize)
__device__ int      g_ready;    // k_prep scan-done flag  (reset by k_loss finalize)

// ---------------- dtype detection (warp-parallel, deterministic) ----------------
__device__ __forceinline__ void detect_warp(const void* gt, const void* fg,
                                            int t, int* fl) {
    if (t < 32) {
        const int* w = (const int*)gt;
        int any = w[2 * t + 1] | w[2 * (t + 32) + 1];
        const uchar4* f4 = (const uchar4*)fg;
        uchar4 q0 = f4[t], q1 = f4[t + 32];
        int nb = q0.y | q0.z | q0.w | q1.y | q1.z | q1.w;
        unsigned b1 = __ballot_sync(0xffffffffu, any != 0);
        unsigned b2 = __ballot_sync(0xffffffffu, nb != 0);
        if (t == 0) { fl[0] = (b1 == 0) ? 1 : 0; fl[1] = (b2 == 0) ? 1 : 0; }
    }
}
__device__ __forceinline__ int get_gt(const void* p, int i, int gt64) {
    return gt64 ? (int)((const long long*)p)[i] : ((const int*)p)[i];
}
__device__ __forceinline__ bool get_fg(const void* p, int i, int fg32) {
    return fg32 ? (((const int*)p)[i] != 0) : (((const unsigned char*)p)[i] != 0);
}

// ---------------- mma / ldmatrix helpers ----------------
__device__ __forceinline__ void mma16816(float* c, const uint32_t* a, const uint32_t* b) {
    asm volatile(
        "mma.sync.aligned.m16n8k16.row.col.f32.bf16.bf16.f32 "
        "{%0,%1,%2,%3}, {%4,%5,%6,%7}, {%8,%9}, {%0,%1,%2,%3};"
        : "+f"(c[0]), "+f"(c[1]), "+f"(c[2]), "+f"(c[3])
        : "r"(a[0]), "r"(a[1]), "r"(a[2]), "r"(a[3]), "r"(b[0]), "r"(b[1]));
}
#define LDMX4(r, addr) \
    asm volatile("ldmatrix.sync.aligned.m8n8.x4.shared.b16 {%0,%1,%2,%3}, [%4];" \
                 : "=r"((r)[0]), "=r"((r)[1]), "=r"((r)[2]), "=r"((r)[3]) : "r"(addr))
__device__ __forceinline__ uint32_t smem_u32(const void* p) {
    uint32_t a;
    asm("{ .reg .u64 t; cvta.to.shared.u64 t, %1; cvt.u32.u64 %0, t; }" : "=r"(a) : "l"(p));
    return a;
}

// ---------------- kernels ----------------
// Launch #1: fused histogram + (last block) scan + placement.
__global__ void __launch_bounds__(128) k_prep(const float* __restrict__ pred,
                                              const void* __restrict__ gt,
                                              const void* __restrict__ fg) {
    int b = blockIdx.y, ch = blockIdx.x, t = threadIdx.x;
    int wid = t >> 5, lane = t & 31;
    __shared__ int hw[4][Gn];          // per-warp group histogram
    __shared__ int fl[2];
    __shared__ int s_last;
    detect_warp(gt, fg, t, fl);
    if (t < 4 * Gn) ((int*)hw)[t] = 0;
    __syncthreads();
    int gt64 = fl[0], fg32 = fl[1];
    int j = ch * 128 + t;
    bool m = get_fg(fg, b * Nn + j, fg32);
    int gv = m ? get_gt(gt, b * Nn + j, gt64) : -1;

    // warp-level group matching: rank within warp + per-warp counts
    unsigned mm = __match_any_sync(0xffffffffu, gv);
    unsigned ltm = mm & ((1u << lane) - 1u);
    int rwarp = __popc(ltm);
    if (m && ltm == 0) atomicAdd(&hw[wid][gv], __popc(mm));
    __syncthreads();
    if (t < Gn) g_ccnt[b][ch][t] = hw[0][t] + hw[1][t] + hw[2][t] + hw[3][t];

    // signal arrival early (histogram for this chunk is published)
    if (t == 0) {
        __threadfence();
        int prev = atomicAdd(&g_arrive, 1);
        s_last = (prev == NCH * Bn - 1) ? 1 : 0;
    }

    // ---- scan-independent work: normalize + bf16 split into uint4 registers ----
    float4 fv[8];
    uint4 hi4[4], lo4[4];
    if (m) {
        const float4* s = (const float4*)(pred + ((size_t)b * Nn + j) * Dn);
        float ss = 0.f;
#pragma unroll
        for (int c = 0; c < 8; c++) {
            fv[c] = s[c];
            ss += fv[c].x * fv[c].x + fv[c].y * fv[c].y
                + fv[c].z * fv[c].z + fv[c].w * fv[c].w;
        }
        float inv = 1.0f / fmaxf(sqrtf(ss), EPSf);
#pragma unroll
        for (int c = 0; c < 8; c++) {
            fv[c].x *= inv; fv[c].y *= inv; fv[c].z *= inv; fv[c].w *= inv;
        }
#pragma unroll
        for (int c = 0; c < 4; c++) {
            // 8 floats -> 4 hi-words + 4 lo-words per uint4 pair
            float4 u = fv[2 * c], v = fv[2 * c + 1];
            __nv_bfloat162 h0 = __floats2bfloat162_rn(u.x, u.y);
            __nv_bfloat162 h1 = __floats2bfloat162_rn(u.z, u.w);
            __nv_bfloat162 h2 = __floats2bfloat162_rn(v.x, v.y);
            __nv_bfloat162 h3 = __floats2bfloat162_rn(v.z, v.w);
            __nv_bfloat162 l0 = __floats2bfloat162_rn(u.x - __bfloat162float(h0.x),
                                                      u.y - __bfloat162float(h0.y));
            __nv_bfloat162 l1 = __floats2bfloat162_rn(u.z - __bfloat162float(h1.x),
                                                      u.w - __bfloat162float(h1.y));
            __nv_bfloat162 l2 = __floats2bfloat162_rn(v.x - __bfloat162float(h2.x),
                                                      v.y - __bfloat162float(h2.y));
            __nv_bfloat162 l3 = __floats2bfloat162_rn(v.z - __bfloat162float(h3.x),
                                                      v.w - __bfloat162float(h3.y));
            hi4[c] = make_uint4(*(uint32_t*)&h0, *(uint32_t*)&h1,
                                *(uint32_t*)&h2, *(uint32_t*)&h3);
            lo4[c] = make_uint4(*(uint32_t*)&l0, *(uint32_t*)&l1,
                                *(uint32_t*)&l2, *(uint32_t*)&l3);
        }
    }

    // ---- barrier: last block scans, others spin ----
    __syncthreads();
    if (s_last) {
        if (t < Bn * Gn) {
            int bb2 = t / Gn, g = t % Gn;
            int v[NCH];
#pragma unroll
            for (int c = 0; c < NCH; c++) v[c] = g_ccnt[bb2][c][g];   // batched: MLP=50
            int run = 0;
#pragma unroll
            for (int c = 0; c < NCH; c++) { g_cbase[bb2][c][g] = run; run += v[c]; }
            g_cnt[bb2][g] = run;
        }
        __syncthreads();
        if (t < Bn) {
            int v[Gn];
#pragma unroll
            for (int g = 0; g < Gn; g++) v[g] = g_cnt[t][g];          // batched: MLP=20
            int acc = 0;
#pragma unroll
            for (int g = 0; g < Gn; g++) { g_offs[t][g] = acc; acc += v[g]; }
            g_offs[t][Gn] = acc;
        }
        __syncthreads();
        if (t < Bn * Gn) {
            int bb2 = t / Gn, g = t % Gn, o = g_offs[bb2][g];
#pragma unroll
            for (int c = 0; c < NCH; c++) g_cbase[bb2][c][g] += o;
        }
        __syncthreads();
        if (t == 0) { __threadfence(); atomicExch(&g_ready, 1); }
    } else if (t == 0) {
        while (atomicAdd(&g_ready, 0) == 0) { __nanosleep(32); }
    }
    __syncthreads();

    // ---- post-barrier: pos + vectorized stores ----
    if (!m) return;
    int r = rwarp;
#pragma unroll
    for (int w2 = 0; w2 < 4; w2++) if (w2 < wid) r += hw[w2][gv];
    int pos = g_cbase[b][ch][gv] + r;
    g_mgrp[b * Nn + pos] = (unsigned char)gv;
    g_slot[b * Nn + j] = pos;

    float4* d = (float4*)(g_mcoeff + ((size_t)b * Nn + pos) * Dn);
#pragma unroll
    for (int c = 0; c < 8; c++) d[c] = fv[c];

    uint4* ea = g_ea4 + ((size_t)b * Nn + pos) * 12;
    uint4* eb = g_eb4 + ((size_t)b * Nn + pos) * 12;
#pragma unroll
    for (int c = 0; c < 4; c++) {
        ea[c] = hi4[c]; ea[4 + c] = hi4[c]; ea[8 + c] = lo4[c];   // A: hi|hi|lo
        eb[c] = hi4[c]; eb[4 + c] = lo4[c]; eb[8 + c] = hi4[c];   // B: hi|lo|hi
    }
}

// Launch #2 (hot): HMMA negmax, K=96, warp-uniform fast-path epilogue.
__global__ void __launch_bounds__(128, 6) k_negmax() {
    extern __shared__ char smem[];
    const int b = blockIdx.y;
    const int A = g_offs[b][Gn];
    const int mbase = blockIdx.x * MT;
    if (mbase >= A) return;
    const int z = blockIdx.z;
    const int tid = threadIdx.x;
    const int wid = tid >> 5, lane = tid & 31;
    const int q = lane >> 2, t4 = lane & 3;
    const int m0 = mbase + wid * 32;
    const int r0 = m0 + q,  r1 = r0 + 8;    // block X rows
    const int r2 = r0 + 16, r3 = r0 + 24;   // block Y rows
    const size_t bNn = (size_t)b * Nn;

    // A fragments: 6 ksteps x 4 regs x 2 row-blocks
    uint32_t aX[6][4], aY[6][4];
    {
        const uint32_t* e0 = (const uint32_t*)(g_ea4 + (bNn + r0) * 12) + t4;
        const uint32_t* e1 = (const uint32_t*)(g_ea4 + (bNn + r1) * 12) + t4;
        const uint32_t* e2 = (const uint32_t*)(g_ea4 + (bNn + r2) * 12) + t4;
        const uint32_t* e3 = (const uint32_t*)(g_ea4 + (bNn + r3) * 12) + t4;
#pragma unroll
        for (int s = 0; s < 6; s++) {
            aX[s][0] = e0[s * 8]; aX[s][1] = e1[s * 8];
            aX[s][2] = e0[s * 8 + 4]; aX[s][3] = e1[s * 8 + 4];
            aY[s][0] = e2[s * 8]; aY[s][1] = e3[s * 8];
            aY[s][2] = e2[s * 8 + 4]; aY[s][3] = e3[s * 8 + 4];
        }
    }
    int gi0 = (int)g_mgrp[bNn + min(r0, A - 1)];
    int gi1 = (int)g_mgrp[bNn + min(r1, A - 1)];
    int gi2 = (int)g_mgrp[bNn + min(r2, A - 1)];
    int gi3 = (int)g_mgrp[bNn + min(r3, A - 1)];
    int lo0 = g_offs[b][gi0], hi0 = g_offs[b][gi0 + 1];
    int lo1 = g_offs[b][gi1], hi1 = g_offs[b][gi1 + 1];
    int lo2 = g_offs[b][gi2], hi2 = g_offs[b][gi2 + 1];
    int lo3 = g_offs[b][gi3], hi3 = g_offs[b][gi3 + 1];
    const int wlo = __reduce_min_sync(0xffffffffu, min(min(lo0, lo1), min(lo2, lo3)));
    const int whi = __reduce_max_sync(0xffffffffu, max(max(hi0, hi1), max(hi2, hi3)));
    float nm0 = -1e30f, nm1 = -1e30f, nm2 = -1e30f, nm3 = -1e30f;

    const uint32_t sbase = smem_u32(smem);
    const uint32_t ldbase = sbase + (uint32_t)((lane & 7) * BSTRIDE + 16 * (lane >> 3));
    const int ntiles = (A + NT - 1) / NT;

    for (int it = z; it < ntiles; it += NSPLIT) {
        __syncthreads();
        const uint4* src = g_eb4 + (bNn + (size_t)it * NT) * 12;
        for (int idx = tid; idx < NT * 12; idx += 128) {
            int row = idx / 12, c = idx - row * 12;
            *(uint4*)(smem + row * BSTRIDE + c * 16) = src[idx];
        }
        __syncthreads();

#pragma unroll 1
        for (int chk = 0; chk < NT / 8; chk++) {
            uint32_t addr = ldbase + (uint32_t)(chk * 8 * BSTRIDE);
            uint32_t bb[12];
            LDMX4(bb + 0, addr);
            LDMX4(bb + 4, addr + 64u);
            LDMX4(bb + 8, addr + 128u);
            float cX[4] = {0.f, 0.f, 0.f, 0.f};
            float cY[4] = {0.f, 0.f, 0.f, 0.f};
#pragma unroll
            for (int s = 0; s < 6; s++) {
                mma16816(cX, aX[s], bb + 2 * s);
                mma16816(cY, aY[s], bb + 2 * s);
            }
            const int c0 = it * NT + chk * 8;
            if ((c0 + 8 <= wlo || c0 >= whi) && (c0 + 8 <= A)) {
                nm0 = fmaxf(nm0, fmaxf(cX[0], cX[1]));
                nm1 = fmaxf(nm1, fmaxf(cX[2], cX[3]));
                nm2 = fmaxf(nm2, fmaxf(cY[0], cY[1]));
                nm3 = fmaxf(nm3, fmaxf(cY[2], cY[3]));
            } else {
                int cd0 = c0 + 2 * t4, cd1 = cd0 + 1;
                bool v0 = cd0 < A, v1 = cd1 < A;
                if (v0 && (cd0 < lo0 || cd0 >= hi0)) nm0 = fmaxf(nm0, cX[0]);
                if (v1 && (cd1 < lo0 || cd1 >= hi0)) nm0 = fmaxf(nm0, cX[1]);
                if (v0 && (cd0 < lo1 || cd0 >= hi1)) nm1 = fmaxf(nm1, cX[2]);
                if (v1 && (cd1 < lo1 || cd1 >= hi1)) nm1 = fmaxf(nm1, cX[3]);
                if (v0 && (cd0 < lo2 || cd0 >= hi2)) nm2 = fmaxf(nm2, cY[0]);
                if (v1 && (cd1 < lo2 || cd1 >= hi2)) nm2 = fmaxf(nm2, cY[1]);
                if (v0 && (cd0 < lo3 || cd0 >= hi3)) nm3 = fmaxf(nm3, cY[2]);
                if (v1 && (cd1 < lo3 || cd1 >= hi3)) nm3 = fmaxf(nm3, cY[3]);
            }
        }
    }

    nm0 = fmaxf(nm0, __shfl_xor_sync(0xffffffffu, nm0, 1));
    nm0 = fmaxf(nm0, __shfl_xor_sync(0xffffffffu, nm0, 2));
    nm1 = fmaxf(nm1, __shfl_xor_sync(0xffffffffu, nm1, 1));
    nm1 = fmaxf(nm1, __shfl_xor_sync(0xffffffffu, nm1, 2));
    nm2 = fmaxf(nm2, __shfl_xor_sync(0xffffffffu, nm2, 1));
    nm2 = fmaxf(nm2, __shfl_xor_sync(0xffffffffu, nm2, 2));
    nm3 = fmaxf(nm3, __shfl_xor_sync(0xffffffffu, nm3, 1));
    nm3 = fmaxf(nm3, __shfl_xor_sync(0xffffffffu, nm3, 2));
    if (t4 == 0) {
        if (r0 < A) g_negS[z][bNn + r0] = nm0;
        if (r1 < A) g_negS[z][bNn + r1] = nm1;
        if (r2 < A) g_negS[z][bNn + r2] = nm2;
        if (r3 < A) g_negS[z][bNn + r3] = nm3;
    }
}

// Launch #3: triplet loss + block reduction + fused finalize (+ counter reset)
__global__ void __launch_bounds__(256) k_loss(const float* __restrict__ posr,
                                              const void* __restrict__ gt,
                                              const void* __restrict__ fg,
                                              float* __restrict__ out, int out_size) {
    __shared__ int fl[2];
    detect_warp(gt, fg, threadIdx.x, fl);
    __syncthreads();
    int gt64 = fl[0], fg32 = fl[1];

    int i = blockIdx.x * blockDim.x + threadIdx.x;
    float per = 0.f;
    int cntv = 0;
    if (i < Bn * Nn && get_fg(fg, i, fg32)) {
        int b = i / Nn;
        int g = get_gt(gt, i, gt64);
        int cnt = g_cnt[b][g];
        int np = cnt - 1;
        int A = g_offs[b][Gn];
        if (np >= 1 && (A - cnt) > 0) {
            int slot = g_slot[i];
            int base = g_offs[b][g];
            int p = slot - base;

            float u = posr[i];
            int k = (int)floorf(u * (float)np);
            k = min(max(k, 0), np - 1);
            int sl = (k < p) ? k : k + 1;   // skip self in ordered group list
            int jslot = base + sl;

            const float4* ci = (const float4*)(g_mcoeff + ((size_t)b * Nn + slot) * Dn);
            const float4* cp = (const float4*)(g_mcoeff + ((size_t)b * Nn + jslot) * Dn);
            float ss = 0.f;
#pragma unroll
            for (int c = 0; c < 8; c++) {
                float4 u4 = ci[c], v4 = cp[c];
                float d0 = u4.x - v4.x, d1 = u4.y - v4.y;
                float d2 = u4.z - v4.z, d3 = u4.w - v4.w;
                ss = fmaf(d0, d0, ss); ss = fmaf(d1, d1, ss);
                ss = fmaf(d2, d2, ss); ss = fmaf(d3, d3, ss);
            }
            float pos_d = sqrtf(ss + EPSf);

            float s = g_negS[0][(size_t)b * Nn + slot];
#pragma unroll
            for (int zz = 1; zz < NSPLIT; zz++)
                s = fmaxf(s, g_negS[zz][(size_t)b * Nn + slot]);
            float nd2 = 2.0f - 2.0f * s;
            if (nd2 < 0.f) nd2 = 0.f;
            float neg_d = sqrtf(nd2 + EPSf);

            per = pos_d - neg_d + MARGINf;
            if (per < 0.f) per = 0.f;
            cntv = 1;
        }
    }
    double pv = (double)per;
#pragma unroll
    for (int o = 16; o > 0; o >>= 1) {
        pv   += __shfl_down_sync(0xffffffffu, pv, o);
        cntv += __shfl_down_sync(0xffffffffu, cntv, o);
    }
    __shared__ double sp[8];
    __shared__ int    sn[8];
    int w = threadIdx.x >> 5, l = threadIdx.x & 31;
    if (l == 0) { sp[w] = pv; sn[w] = cntv; }
    __syncthreads();
    if (w == 0) {
        double v = (l < 8) ? sp[l] : 0.0;
        int    n = (l < 8) ? sn[l] : 0;
#pragma unroll
        for (int o = 4; o > 0; o >>= 1) {
            v += __shfl_down_sync(0xffffffffu, v, o);
            n += __shfl_down_sync(0xffffffffu, n, o);
        }
        if (l == 0) {
            if (v != 0.0 || n != 0) {
                atomicAdd(&g_sum, v);
                atomicAdd(&g_num, n);
            }
            __threadfence();
            int prev = atomicAdd(&g_done, 1);
            if (prev == (int)gridDim.x - 1) {
                double fs = atomicAdd(&g_sum, 0.0);
                int    fn = atomicAdd(&g_num, 0);
                float val = (fn > 0) ? (float)(fs / (double)fn) : 0.0f;
                for (int o2 = 0; o2 < out_size; o2++) out[o2] = (o2 == 0) ? val : 0.0f;
                // reset all inter-launch state for the next graph replay
                g_sum = 0.0; g_num = 0; g_done = 0; g_arrive = 0; g_ready = 0;
            }
        }
    }
}

// ---------------- launch ----------------
extern "C" void kernel_launch(void* const* d_in, const int* in_sizes, int n_in,
                              void* d_out, int out_size) {
    const float* pred = (const float*)d_in[0];
    const float* posr = (const float*)d_in[1];
    const void*  gt   = (const void*)d_in[2];
    const void*  fg   = (const void*)d_in[3];
    float* out = (float*)d_out;

    dim3 gc(NCH, Bn);
    k_prep<<<gc, 128>>>(pred, gt, fg);
    dim3 gn(Nn / MT, Bn, NSPLIT);
    k_negmax<<<gn, 128, SMEM_NEG>>>();
    k_loss<<<(Bn * Nn + 255) / 256, 256>>>(posr, gt, fg, out, out_size);
}

// round 15
// speedup vs baseline: 1.3524x; 1.3524x over previous
#include <cuda_runtime.h>
#include <cuda_bf16.h>
#include <math.h>
#include <stdint.h>

#define Bn 4
#define Nn 6400
#define Dn 32
#define Gn 20
#define NCH 50            // Nn / 128 chunks
#define MARGINf 0.3f
#define EPSf 1e-12f
#define MT 128            // anchors per block (4 warps x 2 x m16)
#define NT 128            // candidate tile rows
#define NSPLIT 9
#define BSTRIDE 208       // smem bytes per candidate row (192B data + 16B pad)
#define SMEM_NEG (NT * BSTRIDE)

// ---------------- scratch (device globals) ----------------
// ext rows (K=96): A = [hi|hi|lo] (48 u32), B = [hi|lo|hi] (192B = 12 uint4).
// dot = hi*hi + hi*lo + lo*hi  (lo*lo dropped, ~2e-5 abs err on unit vectors)
__device__ float    g_mcoeff[Bn * Nn * Dn];  // compacted fp32 coeffs (for pos_d)
__device__ uint32_t g_ea[Bn * Nn * 48];      // anchor-ext rows
__device__ uint4    g_eb4[Bn * Nn * 12];     // cand-ext rows
__device__ unsigned char g_mgrp[Bn * Nn];    // compact slot -> group id
__device__ int      g_slot[Bn * Nn];         // original j -> compact slot
__device__ float    g_negS[NSPLIT][Bn * Nn]; // per-split max sim over different-group fg
__device__ int      g_ccnt[Bn][NCH][Gn];
__device__ int      g_cbase[Bn][NCH][Gn];
__device__ int      g_cnt[Bn][Gn];
__device__ int      g_offs[Bn][Gn + 1];
__device__ double   g_sum;
__device__ int      g_num;
__device__ int      g_done;
__device__ int      g_arrive;   // k_prep arrival counter (reset by k_loss finalize)
__device__ int      g_ready;    // k_prep scan-done flag  (reset by k_loss finalize)

// ---------------- dtype detection (warp-parallel, deterministic) ----------------
__device__ __forceinline__ void detect_warp(const void* gt, const void* fg,
                                            int t, int* fl) {
    if (t < 32) {
        const int* w = (const int*)gt;
        int any = w[2 * t + 1] | w[2 * (t + 32) + 1];
        const uchar4* f4 = (const uchar4*)fg;
        uchar4 q0 = f4[t], q1 = f4[t + 32];
        int nb = q0.y | q0.z | q0.w | q1.y | q1.z | q1.w;
        unsigned b1 = __ballot_sync(0xffffffffu, any != 0);
        unsigned b2 = __ballot_sync(0xffffffffu, nb != 0);
        if (t == 0) { fl[0] = (b1 == 0) ? 1 : 0; fl[1] = (b2 == 0) ? 1 : 0; }
    }
}
__device__ __forceinline__ int get_gt(const void* p, int i, int gt64) {
    return gt64 ? (int)((const long long*)p)[i] : ((const int*)p)[i];
}
__device__ __forceinline__ bool get_fg(const void* p, int i, int fg32) {
    return fg32 ? (((const int*)p)[i] != 0) : (((const unsigned char*)p)[i] != 0);
}

// ---------------- mma / ldmatrix helpers ----------------
__device__ __forceinline__ void mma16816(float* c, const uint32_t* a, const uint32_t* b) {
    asm volatile(
        "mma.sync.aligned.m16n8k16.row.col.f32.bf16.bf16.f32 "
        "{%0,%1,%2,%3}, {%4,%5,%6,%7}, {%8,%9}, {%0,%1,%2,%3};"
        : "+f"(c[0]), "+f"(c[1]), "+f"(c[2]), "+f"(c[3])
        : "r"(a[0]), "r"(a[1]), "r"(a[2]), "r"(a[3]), "r"(b[0]), "r"(b[1]));
}
#define LDMX4(r, addr) \
    asm volatile("ldmatrix.sync.aligned.m8n8.x4.shared.b16 {%0,%1,%2,%3}, [%4];" \
                 : "=r"((r)[0]), "=r"((r)[1]), "=r"((r)[2]), "=r"((r)[3]) : "r"(addr))
__device__ __forceinline__ uint32_t smem_u32(const void* p) {
    uint32_t a;
    asm("{ .reg .u64 t; cvta.to.shared.u64 t, %1; cvt.u32.u64 %0, t; }" : "=r"(a) : "l"(p));
    return a;
}

// ---------------- kernels ----------------
// Launch #1: fused histogram + (last block) scan + placement.
__global__ void __launch_bounds__(128) k_prep(const float* __restrict__ pred,
                                              const void* __restrict__ gt,
                                              const void* __restrict__ fg) {
    int b = blockIdx.y, ch = blockIdx.x, t = threadIdx.x;
    int wid = t >> 5, lane = t & 31;
    __shared__ int hw[4][Gn];          // per-warp group histogram
    __shared__ int fl[2];
    __shared__ int s_last;
    detect_warp(gt, fg, t, fl);
    if (t < 4 * Gn) ((int*)hw)[t] = 0;
    __syncthreads();
    int gt64 = fl[0], fg32 = fl[1];
    int j = ch * 128 + t;
    bool m = get_fg(fg, b * Nn + j, fg32);
    int gv = m ? get_gt(gt, b * Nn + j, gt64) : -1;

    // warp-level group matching: rank within warp + per-warp counts
    unsigned mm = __match_any_sync(0xffffffffu, gv);
    unsigned ltm = mm & ((1u << lane) - 1u);
    int rwarp = __popc(ltm);
    if (m && ltm == 0) atomicAdd(&hw[wid][gv], __popc(mm));
    __syncthreads();
    if (t < Gn) g_ccnt[b][ch][t] = hw[0][t] + hw[1][t] + hw[2][t] + hw[3][t];

    // arrival: last block performs the scan, others spin
    if (t == 0) {
        __threadfence();
        int prev = atomicAdd(&g_arrive, 1);
        s_last = (prev == NCH * Bn - 1) ? 1 : 0;
    }
    __syncthreads();
    if (s_last) {
        if (t < Bn * Gn) {
            int bb2 = t / Gn, g = t % Gn;
            int v[NCH];
#pragma unroll
            for (int c = 0; c < NCH; c++) v[c] = g_ccnt[bb2][c][g];   // batched: MLP=50
            int run = 0;
#pragma unroll
            for (int c = 0; c < NCH; c++) { g_cbase[bb2][c][g] = run; run += v[c]; }
            g_cnt[bb2][g] = run;
        }
        __syncthreads();
        if (t < Bn) {
            int v[Gn];
#pragma unroll
            for (int g = 0; g < Gn; g++) v[g] = g_cnt[t][g];          // batched: MLP=20
            int acc = 0;
#pragma unroll
            for (int g = 0; g < Gn; g++) { g_offs[t][g] = acc; acc += v[g]; }
            g_offs[t][Gn] = acc;
        }
        __syncthreads();
        if (t < Bn * Gn) {
            int bb2 = t / Gn, g = t % Gn, o = g_offs[bb2][g];
#pragma unroll
            for (int c = 0; c < NCH; c++) g_cbase[bb2][c][g] += o;
        }
        __syncthreads();
        if (t == 0) { __threadfence(); atomicExch(&g_ready, 1); }
    } else if (t == 0) {
        while (atomicAdd(&g_ready, 0) == 0) { __nanosleep(64); }
    }
    __syncthreads();

    // placement + normalization + ext-row build
    if (!m) return;
    int r = rwarp;
#pragma unroll
    for (int w2 = 0; w2 < 4; w2++) if (w2 < wid) r += hw[w2][gv];
    int pos = g_cbase[b][ch][gv] + r;
    g_mgrp[b * Nn + pos] = (unsigned char)gv;
    g_slot[b * Nn + j] = pos;

    const float4* s = (const float4*)(pred + ((size_t)b * Nn + j) * Dn);
    float f[Dn];
    float ss = 0.f;
#pragma unroll
    for (int c = 0; c < 8; c++) {
        float4 v = s[c];
        f[4 * c] = v.x; f[4 * c + 1] = v.y; f[4 * c + 2] = v.z; f[4 * c + 3] = v.w;
        ss += v.x * v.x + v.y * v.y + v.z * v.z + v.w * v.w;
    }
    float inv = 1.0f / fmaxf(sqrtf(ss), EPSf);
#pragma unroll
    for (int c = 0; c < Dn; c++) f[c] *= inv;
    float4* d = (float4*)(g_mcoeff + ((size_t)b * Nn + pos) * Dn);
#pragma unroll
    for (int c = 0; c < 8; c++)
        d[c] = make_float4(f[4 * c], f[4 * c + 1], f[4 * c + 2], f[4 * c + 3]);

    uint32_t hi[16], lo[16];
#pragma unroll
    for (int c = 0; c < 16; c++) {
        float a0 = f[2 * c], a1 = f[2 * c + 1];
        __nv_bfloat162 h2 = __floats2bfloat162_rn(a0, a1);
        float l0 = a0 - __bfloat162float(h2.x);
        float l1 = a1 - __bfloat162float(h2.y);
        __nv_bfloat162 l2 = __floats2bfloat162_rn(l0, l1);
        hi[c] = *(uint32_t*)&h2;
        lo[c] = *(uint32_t*)&l2;
    }
    uint32_t* ea = g_ea + ((size_t)b * Nn + pos) * 48;
    uint32_t* eb = (uint32_t*)(g_eb4 + ((size_t)b * Nn + pos) * 12);
#pragma unroll
    for (int c = 0; c < 16; c++) {
        ea[c] = hi[c]; ea[16 + c] = hi[c]; ea[32 + c] = lo[c];   // A: hi|hi|lo
        eb[c] = hi[c]; eb[16 + c] = lo[c]; eb[32 + c] = hi[c];   // B: hi|lo|hi
    }
}

// Launch #2 (hot): HMMA negmax, K=96, warp-uniform fast-path epilogue.
__global__ void __launch_bounds__(128, 6) k_negmax() {
    extern __shared__ char smem[];
    const int b = blockIdx.y;
    const int A = g_offs[b][Gn];
    const int mbase = blockIdx.x * MT;
    if (mbase >= A) return;
    const int z = blockIdx.z;
    const int tid = threadIdx.x;
    const int wid = tid >> 5, lane = tid & 31;
    const int q = lane >> 2, t4 = lane & 3;
    const int m0 = mbase + wid * 32;
    const int r0 = m0 + q,  r1 = r0 + 8;    // block X rows
    const int r2 = r0 + 16, r3 = r0 + 24;   // block Y rows
    const size_t bNn = (size_t)b * Nn;

    // A fragments: 6 ksteps x 4 regs x 2 row-blocks
    uint32_t aX[6][4], aY[6][4];
    {
        const uint32_t* e0 = g_ea + (bNn + r0) * 48 + t4;
        const uint32_t* e1 = g_ea + (bNn + r1) * 48 + t4;
        const uint32_t* e2 = g_ea + (bNn + r2) * 48 + t4;
        const uint32_t* e3 = g_ea + (bNn + r3) * 48 + t4;
#pragma unroll
        for (int s = 0; s < 6; s++) {
            aX[s][0] = e0[s * 8]; aX[s][1] = e1[s * 8];
            aX[s][2] = e0[s * 8 + 4]; aX[s][3] = e1[s * 8 + 4];
            aY[s][0] = e2[s * 8]; aY[s][1] = e3[s * 8];
            aY[s][2] = e2[s * 8 + 4]; aY[s][3] = e3[s * 8 + 4];
        }
    }
    int gi0 = (int)g_mgrp[bNn + min(r0, A - 1)];
    int gi1 = (int)g_mgrp[bNn + min(r1, A - 1)];
    int gi2 = (int)g_mgrp[bNn + min(r2, A - 1)];
    int gi3 = (int)g_mgrp[bNn + min(r3, A - 1)];
    int lo0 = g_offs[b][gi0], hi0 = g_offs[b][gi0 + 1];
    int lo1 = g_offs[b][gi1], hi1 = g_offs[b][gi1 + 1];
    int lo2 = g_offs[b][gi2], hi2 = g_offs[b][gi2 + 1];
    int lo3 = g_offs[b][gi3], hi3 = g_offs[b][gi3 + 1];
    const int wlo = __reduce_min_sync(0xffffffffu, min(min(lo0, lo1), min(lo2, lo3)));
    const int whi = __reduce_max_sync(0xffffffffu, max(max(hi0, hi1), max(hi2, hi3)));
    float nm0 = -1e30f, nm1 = -1e30f, nm2 = -1e30f, nm3 = -1e30f;

    const uint32_t sbase = smem_u32(smem);
    const uint32_t ldbase = sbase + (uint32_t)((lane & 7) * BSTRIDE + 16 * (lane >> 3));
    const int ntiles = (A + NT - 1) / NT;

    for (int it = z; it < ntiles; it += NSPLIT) {
        __syncthreads();
        const uint4* src = g_eb4 + (bNn + (size_t)it * NT) * 12;
        for (int idx = tid; idx < NT * 12; idx += 128) {
            int row = idx / 12, c = idx - row * 12;
            *(uint4*)(smem + row * BSTRIDE + c * 16) = src[idx];
        }
        __syncthreads();

#pragma unroll 1
        for (int chk = 0; chk < NT / 8; chk++) {
            uint32_t addr = ldbase + (uint32_t)(chk * 8 * BSTRIDE);
            uint32_t bb[12];
            LDMX4(bb + 0, addr);
            LDMX4(bb + 4, addr + 64u);
            LDMX4(bb + 8, addr + 128u);
            float cX[4] = {0.f, 0.f, 0.f, 0.f};
            float cY[4] = {0.f, 0.f, 0.f, 0.f};
#pragma unroll
            for (int s = 0; s < 6; s++) {
                mma16816(cX, aX[s], bb + 2 * s);
                mma16816(cY, aY[s], bb + 2 * s);
            }
            const int c0 = it * NT + chk * 8;
            if ((c0 + 8 <= wlo || c0 >= whi) && (c0 + 8 <= A)) {
                nm0 = fmaxf(nm0, fmaxf(cX[0], cX[1]));
                nm1 = fmaxf(nm1, fmaxf(cX[2], cX[3]));
                nm2 = fmaxf(nm2, fmaxf(cY[0], cY[1]));
                nm3 = fmaxf(nm3, fmaxf(cY[2], cY[3]));
            } else {
                int cd0 = c0 + 2 * t4, cd1 = cd0 + 1;
                bool v0 = cd0 < A, v1 = cd1 < A;
                if (v0 && (cd0 < lo0 || cd0 >= hi0)) nm0 = fmaxf(nm0, cX[0]);
                if (v1 && (cd1 < lo0 || cd1 >= hi0)) nm0 = fmaxf(nm0, cX[1]);
                if (v0 && (cd0 < lo1 || cd0 >= hi1)) nm1 = fmaxf(nm1, cX[2]);
                if (v1 && (cd1 < lo1 || cd1 >= hi1)) nm1 = fmaxf(nm1, cX[3]);
                if (v0 && (cd0 < lo2 || cd0 >= hi2)) nm2 = fmaxf(nm2, cY[0]);
                if (v1 && (cd1 < lo2 || cd1 >= hi2)) nm2 = fmaxf(nm2, cY[1]);
                if (v0 && (cd0 < lo3 || cd0 >= hi3)) nm3 = fmaxf(nm3, cY[2]);
                if (v1 && (cd1 < lo3 || cd1 >= hi3)) nm3 = fmaxf(nm3, cY[3]);
            }
        }
    }

    nm0 = fmaxf(nm0, __shfl_xor_sync(0xffffffffu, nm0, 1));
    nm0 = fmaxf(nm0, __shfl_xor_sync(0xffffffffu, nm0, 2));
    nm1 = fmaxf(nm1, __shfl_xor_sync(0xffffffffu, nm1, 1));
    nm1 = fmaxf(nm1, __shfl_xor_sync(0xffffffffu, nm1, 2));
    nm2 = fmaxf(nm2, __shfl_xor_sync(0xffffffffu, nm2, 1));
    nm2 = fmaxf(nm2, __shfl_xor_sync(0xffffffffu, nm2, 2));
    nm3 = fmaxf(nm3, __shfl_xor_sync(0xffffffffu, nm3, 1));
    nm3 = fmaxf(nm3, __shfl_xor_sync(0xffffffffu, nm3, 2));
    if (t4 == 0) {
        if (r0 < A) g_negS[z][bNn + r0] = nm0;
        if (r1 < A) g_negS[z][bNn + r1] = nm1;
        if (r2 < A) g_negS[z][bNn + r2] = nm2;
        if (r3 < A) g_negS[z][bNn + r3] = nm3;
    }
}

// Launch #3: triplet loss + block reduction + fused finalize (+ counter reset)
__global__ void __launch_bounds__(256) k_loss(const float* __restrict__ posr,
                                              const void* __restrict__ gt,
                                              const void* __restrict__ fg,
                                              float* __restrict__ out, int out_size) {
    __shared__ int fl[2];
    detect_warp(gt, fg, threadIdx.x, fl);
    __syncthreads();
    int gt64 = fl[0], fg32 = fl[1];

    int i = blockIdx.x * blockDim.x + threadIdx.x;
    float per = 0.f;
    int cntv = 0;
    if (i < Bn * Nn && get_fg(fg, i, fg32)) {
        int b = i / Nn;
        int g = get_gt(gt, i, gt64);
        int cnt = g_cnt[b][g];
        int np = cnt - 1;
        int A = g_offs[b][Gn];
        if (np >= 1 && (A - cnt) > 0) {
            int slot = g_slot[i];
            int base = g_offs[b][g];
            int p = slot - base;

            float u = posr[i];
            int k = (int)floorf(u * (float)np);
            k = min(max(k, 0), np - 1);
            int sl = (k < p) ? k : k + 1;   // skip self in ordered group list
            int jslot = base + sl;

            const float4* ci = (const float4*)(g_mcoeff + ((size_t)b * Nn + slot) * Dn);
            const float4* cp = (const float4*)(g_mcoeff + ((size_t)b * Nn + jslot) * Dn);
            float ss = 0.f;
#pragma unroll
            for (int c = 0; c < 8; c++) {
                float4 u4 = ci[c], v4 = cp[c];
                float d0 = u4.x - v4.x, d1 = u4.y - v4.y;
                float d2 = u4.z - v4.z, d3 = u4.w - v4.w;
                ss = fmaf(d0, d0, ss); ss = fmaf(d1, d1, ss);
                ss = fmaf(d2, d2, ss); ss = fmaf(d3, d3, ss);
            }
            float pos_d = sqrtf(ss + EPSf);

            float s = g_negS[0][(size_t)b * Nn + slot];
#pragma unroll
            for (int zz = 1; zz < NSPLIT; zz++)
                s = fmaxf(s, g_negS[zz][(size_t)b * Nn + slot]);
            float nd2 = 2.0f - 2.0f * s;
            if (nd2 < 0.f) nd2 = 0.f;
            float neg_d = sqrtf(nd2 + EPSf);

            per = pos_d - neg_d + MARGINf;
            if (per < 0.f) per = 0.f;
            cntv = 1;
        }
    }
    double pv = (double)per;
#pragma unroll
    for (int o = 16; o > 0; o >>= 1) {
        pv   += __shfl_down_sync(0xffffffffu, pv, o);
        cntv += __shfl_down_sync(0xffffffffu, cntv, o);
    }
    __shared__ double sp[8];
    __shared__ int    sn[8];
    int w = threadIdx.x >> 5, l = threadIdx.x & 31;
    if (l == 0) { sp[w] = pv; sn[w] = cntv; }
    __syncthreads();
    if (w == 0) {
        double v = (l < 8) ? sp[l] : 0.0;
        int    n = (l < 8) ? sn[l] : 0;
#pragma unroll
        for (int o = 4; o > 0; o >>= 1) {
            v += __shfl_down_sync(0xffffffffu, v, o);
            n += __shfl_down_sync(0xffffffffu, n, o);
        }
        if (l == 0) {
            if (v != 0.0 || n != 0) {
                atomicAdd(&g_sum, v);
                atomicAdd(&g_num, n);
            }
            __threadfence();
            int prev = atomicAdd(&g_done, 1);
            if (prev == (int)gridDim.x - 1) {
                double fs = atomicAdd(&g_sum, 0.0);
                int    fn = atomicAdd(&g_num, 0);
                float val = (fn > 0) ? (float)(fs / (double)fn) : 0.0f;
                for (int o2 = 0; o2 < out_size; o2++) out[o2] = (o2 == 0) ? val : 0.0f;
                // reset all inter-launch state for the next graph replay
                g_sum = 0.0; g_num = 0; g_done = 0; g_arrive = 0; g_ready = 0;
            }
        }
    }
}

// ---------------- launch ----------------
extern "C" void kernel_launch(void* const* d_in, const int* in_sizes, int n_in,
                              void* d_out, int out_size) {
    const float* pred = (const float*)d_in[0];
    const float* posr = (const float*)d_in[1];
    const void*  gt   = (const void*)d_in[2];
    const void*  fg   = (const void*)d_in[3];
    float* out = (float*)d_out;

    dim3 gc(NCH, Bn);
    k_prep<<<gc, 128>>>(pred, gt, fg);
    dim3 gn(Nn / MT, Bn, NSPLIT);
    k_negmax<<<gn, 128, SMEM_NEG>>>();
    k_loss<<<(Bn * Nn + 255) / 256, 256>>>(posr, gt, fg, out, out_size);
}

// round 16
// speedup vs baseline: 1.4069x; 1.0403x over previous
#include <cuda_runtime.h>
#include <cuda_bf16.h>
#include <math.h>
#include <stdint.h>

#define Bn 4
#define Nn 6400
#define Dn 32
#define Gn 20
#define NCH 50            // Nn / 128 chunks
#define MARGINf 0.3f
#define EPSf 1e-12f
#define MT 128            // anchors per block (4 warps x 2 x m16)
#define NT 128            // candidate tile rows
#define NSPLIT 8
#define BSTRIDE 208       // smem bytes per candidate row (192B data + 16B pad)
#define SMEM_NEG (NT * BSTRIDE)

// ---------------- scratch (device globals) ----------------
// ext rows (K=96): A = [hi|hi|lo] (48 u32), B = [hi|lo|hi] (192B = 12 uint4).
// dot = hi*hi + hi*lo + lo*hi  (lo*lo dropped, ~2e-5 abs err on unit vectors)
__device__ float    g_mcoeff[Bn * Nn * Dn];  // compacted fp32 coeffs (for pos_d)
__device__ uint32_t g_ea[Bn * Nn * 48];      // anchor-ext rows
__device__ uint4    g_eb4[Bn * Nn * 12];     // cand-ext rows
__device__ unsigned char g_mgrp[Bn * Nn];    // compact slot -> group id
__device__ int      g_slot[Bn * Nn];         // original j -> compact slot
__device__ float    g_negS[NSPLIT][Bn * Nn]; // per-split max sim over different-group fg
__device__ int      g_ccnt[Bn][NCH][Gn];
__device__ int      g_cnt[Bn][Gn];
__device__ int      g_offs[Bn][Gn + 1];
__device__ double   g_sum;
__device__ int      g_num;
__device__ int      g_done;
__device__ int      g_arrive;   // k_prep arrival counter (reset by k_loss finalize)

// ---------------- dtype detection (warp-parallel, deterministic) ----------------
__device__ __forceinline__ void detect_warp(const void* gt, const void* fg,
                                            int t, int* fl) {
    if (t < 32) {
        const int* w = (const int*)gt;
        int any = w[2 * t + 1] | w[2 * (t + 32) + 1];
        const uchar4* f4 = (const uchar4*)fg;
        uchar4 q0 = f4[t], q1 = f4[t + 32];
        int nb = q0.y | q0.z | q0.w | q1.y | q1.z | q1.w;
        unsigned b1 = __ballot_sync(0xffffffffu, any != 0);
        unsigned b2 = __ballot_sync(0xffffffffu, nb != 0);
        if (t == 0) { fl[0] = (b1 == 0) ? 1 : 0; fl[1] = (b2 == 0) ? 1 : 0; }
    }
}
__device__ __forceinline__ int get_gt(const void* p, int i, int gt64) {
    return gt64 ? (int)((const long long*)p)[i] : ((const int*)p)[i];
}
__device__ __forceinline__ bool get_fg(const void* p, int i, int fg32) {
    return fg32 ? (((const int*)p)[i] != 0) : (((const unsigned char*)p)[i] != 0);
}

// ---------------- mma / ldmatrix helpers ----------------
__device__ __forceinline__ void mma16816(float* c, const uint32_t* a, const uint32_t* b) {
    asm volatile(
        "mma.sync.aligned.m16n8k16.row.col.f32.bf16.bf16.f32 "
        "{%0,%1,%2,%3}, {%4,%5,%6,%7}, {%8,%9}, {%0,%1,%2,%3};"
        : "+f"(c[0]), "+f"(c[1]), "+f"(c[2]), "+f"(c[3])
        : "r"(a[0]), "r"(a[1]), "r"(a[2]), "r"(a[3]), "r"(b[0]), "r"(b[1]));
}
#define LDMX4(r, addr) \
    asm volatile("ldmatrix.sync.aligned.m8n8.x4.shared.b16 {%0,%1,%2,%3}, [%4];" \
                 : "=r"((r)[0]), "=r"((r)[1]), "=r"((r)[2]), "=r"((r)[3]) : "r"(addr))
__device__ __forceinline__ uint32_t smem_u32(const void* p) {
    uint32_t a;
    asm("{ .reg .u64 t; cvta.to.shared.u64 t, %1; cvt.u32.u64 %0, t; }" : "=r"(a) : "l"(p));
    return a;
}

// ---------------- kernels ----------------
// Launch #1: fused histogram + redundant per-block scan + placement.
// All 200 blocks co-resident; spin only on the arrival counter, then every
// block independently computes its own chunk bases (no serialized scan block).
__global__ void __launch_bounds__(128) k_prep(const float* __restrict__ pred,
                                              const void* __restrict__ gt,
                                              const void* __restrict__ fg) {
    int b = blockIdx.y, ch = blockIdx.x, t = threadIdx.x;
    int wid = t >> 5, lane = t & 31;
    __shared__ int hw[4][Gn];          // per-warp group histogram
    __shared__ int fl[2];
    __shared__ int s_tot[Gn];          // per-group totals (this batch)
    __shared__ int s_cbase[Gn];        // this chunk's group bases
    detect_warp(gt, fg, t, fl);
    if (t < 4 * Gn) ((int*)hw)[t] = 0;
    __syncthreads();
    int gt64 = fl[0], fg32 = fl[1];
    int j = ch * 128 + t;
    bool m = get_fg(fg, b * Nn + j, fg32);
    int gv = m ? get_gt(gt, b * Nn + j, gt64) : -1;

    // warp-level group matching: rank within warp + per-warp counts
    unsigned mm = __match_any_sync(0xffffffffu, gv);
    unsigned ltm = mm & ((1u << lane) - 1u);
    int rwarp = __popc(ltm);
    if (m && ltm == 0) atomicAdd(&hw[wid][gv], __popc(mm));
    __syncthreads();
    if (t < Gn) g_ccnt[b][ch][t] = hw[0][t] + hw[1][t] + hw[2][t] + hw[3][t];

    // publish + wait for all 200 histograms
    if (t == 0) {
        __threadfence();
        atomicAdd(&g_arrive, 1);
        while (atomicAdd(&g_arrive, 0) < NCH * Bn) { __nanosleep(32); }
    }
    __syncthreads();

    // redundant scan (each block computes what it needs; all results identical)
    int pre = 0, tot = 0;
    if (t < Gn) {
        int v[NCH];
#pragma unroll
        for (int c = 0; c < NCH; c++) v[c] = g_ccnt[b][c][t];   // batched: MLP=50
#pragma unroll
        for (int c = 0; c < NCH; c++) { if (c < ch) pre += v[c]; tot += v[c]; }
        s_tot[t] = tot;
    }
    __syncthreads();
    if (t < Gn) {
        int off = 0;
#pragma unroll
        for (int g = 0; g < Gn; g++) if (g < t) off += s_tot[g];
        s_cbase[t] = off + pre;
        if (ch == 0) {                 // one block per batch publishes offs/cnt
            g_offs[b][t] = off;
            g_cnt[b][t] = tot;
            if (t == Gn - 1) g_offs[b][Gn] = off + tot;
        }
    }
    __syncthreads();

    // placement + normalization + ext-row build
    if (!m) return;
    int r = rwarp;
#pragma unroll
    for (int w2 = 0; w2 < 4; w2++) if (w2 < wid) r += hw[w2][gv];
    int pos = s_cbase[gv] + r;
    g_mgrp[b * Nn + pos] = (unsigned char)gv;
    g_slot[b * Nn + j] = pos;

    const float4* s = (const float4*)(pred + ((size_t)b * Nn + j) * Dn);
    float f[Dn];
    float ss = 0.f;
#pragma unroll
    for (int c = 0; c < 8; c++) {
        float4 v = s[c];
        f[4 * c] = v.x; f[4 * c + 1] = v.y; f[4 * c + 2] = v.z; f[4 * c + 3] = v.w;
        ss += v.x * v.x + v.y * v.y + v.z * v.z + v.w * v.w;
    }
    float inv = 1.0f / fmaxf(sqrtf(ss), EPSf);
#pragma unroll
    for (int c = 0; c < Dn; c++) f[c] *= inv;
    float4* d = (float4*)(g_mcoeff + ((size_t)b * Nn + pos) * Dn);
#pragma unroll
    for (int c = 0; c < 8; c++)
        d[c] = make_float4(f[4 * c], f[4 * c + 1], f[4 * c + 2], f[4 * c + 3]);

    uint32_t hi[16], lo[16];
#pragma unroll
    for (int c = 0; c < 16; c++) {
        float a0 = f[2 * c], a1 = f[2 * c + 1];
        __nv_bfloat162 h2 = __floats2bfloat162_rn(a0, a1);
        float l0 = a0 - __bfloat162float(h2.x);
        float l1 = a1 - __bfloat162float(h2.y);
        __nv_bfloat162 l2 = __floats2bfloat162_rn(l0, l1);
        hi[c] = *(uint32_t*)&h2;
        lo[c] = *(uint32_t*)&l2;
    }
    uint32_t* ea = g_ea + ((size_t)b * Nn + pos) * 48;
    uint32_t* eb = (uint32_t*)(g_eb4 + ((size_t)b * Nn + pos) * 12);
#pragma unroll
    for (int c = 0; c < 16; c++) {
        ea[c] = hi[c]; ea[16 + c] = hi[c]; ea[32 + c] = lo[c];   // A: hi|hi|lo
        eb[c] = hi[c]; eb[16 + c] = lo[c]; eb[32 + c] = hi[c];   // B: hi|lo|hi
    }
}

// Launch #2 (hot): HMMA negmax, K=96, warp-uniform fast-path epilogue.
__global__ void __launch_bounds__(128, 6) k_negmax() {
    extern __shared__ char smem[];
    const int b = blockIdx.y;
    const int A = g_offs[b][Gn];
    const int mbase = blockIdx.x * MT;
    if (mbase >= A) return;
    const int z = blockIdx.z;
    const int tid = threadIdx.x;
    const int wid = tid >> 5, lane = tid & 31;
    const int q = lane >> 2, t4 = lane & 3;
    const int m0 = mbase + wid * 32;
    const int r0 = m0 + q,  r1 = r0 + 8;    // block X rows
    const int r2 = r0 + 16, r3 = r0 + 24;   // block Y rows
    const size_t bNn = (size_t)b * Nn;

    // A fragments: 6 ksteps x 4 regs x 2 row-blocks
    uint32_t aX[6][4], aY[6][4];
    {
        const uint32_t* e0 = g_ea + (bNn + r0) * 48 + t4;
        const uint32_t* e1 = g_ea + (bNn + r1) * 48 + t4;
        const uint32_t* e2 = g_ea + (bNn + r2) * 48 + t4;
        const uint32_t* e3 = g_ea + (bNn + r3) * 48 + t4;
#pragma unroll
        for (int s = 0; s < 6; s++) {
            aX[s][0] = e0[s * 8]; aX[s][1] = e1[s * 8];
            aX[s][2] = e0[s * 8 + 4]; aX[s][3] = e1[s * 8 + 4];
            aY[s][0] = e2[s * 8]; aY[s][1] = e3[s * 8];
            aY[s][2] = e2[s * 8 + 4]; aY[s][3] = e3[s * 8 + 4];
        }
    }
    int gi0 = (int)g_mgrp[bNn + min(r0, A - 1)];
    int gi1 = (int)g_mgrp[bNn + min(r1, A - 1)];
    int gi2 = (int)g_mgrp[bNn + min(r2, A - 1)];
    int gi3 = (int)g_mgrp[bNn + min(r3, A - 1)];
    int lo0 = g_offs[b][gi0], hi0 = g_offs[b][gi0 + 1];
    int lo1 = g_offs[b][gi1], hi1 = g_offs[b][gi1 + 1];
    int lo2 = g_offs[b][gi2], hi2 = g_offs[b][gi2 + 1];
    int lo3 = g_offs[b][gi3], hi3 = g_offs[b][gi3 + 1];
    const int wlo = __reduce_min_sync(0xffffffffu, min(min(lo0, lo1), min(lo2, lo3)));
    const int whi = __reduce_max_sync(0xffffffffu, max(max(hi0, hi1), max(hi2, hi3)));
    float nm0 = -1e30f, nm1 = -1e30f, nm2 = -1e30f, nm3 = -1e30f;

    const uint32_t sbase = smem_u32(smem);
    const uint32_t ldbase = sbase + (uint32_t)((lane & 7) * BSTRIDE + 16 * (lane >> 3));
    const int ntiles = (A + NT - 1) / NT;

    for (int it = z; it < ntiles; it += NSPLIT) {
        __syncthreads();
        const uint4* src = g_eb4 + (bNn + (size_t)it * NT) * 12;
        for (int idx = tid; idx < NT * 12; idx += 128) {
            int row = idx / 12, c = idx - row * 12;
            *(uint4*)(smem + row * BSTRIDE + c * 16) = src[idx];
        }
        __syncthreads();

#pragma unroll 1
        for (int chk = 0; chk < NT / 8; chk++) {
            uint32_t addr = ldbase + (uint32_t)(chk * 8 * BSTRIDE);
            uint32_t bb[12];
            LDMX4(bb + 0, addr);
            LDMX4(bb + 4, addr + 64u);
            LDMX4(bb + 8, addr + 128u);
            float cX[4] = {0.f, 0.f, 0.f, 0.f};
            float cY[4] = {0.f, 0.f, 0.f, 0.f};
#pragma unroll
            for (int s = 0; s < 6; s++) {
                mma16816(cX, aX[s], bb + 2 * s);
                mma16816(cY, aY[s], bb + 2 * s);
            }
            const int c0 = it * NT + chk * 8;
            if ((c0 + 8 <= wlo || c0 >= whi) && (c0 + 8 <= A)) {
                nm0 = fmaxf(nm0, fmaxf(cX[0], cX[1]));
                nm1 = fmaxf(nm1, fmaxf(cX[2], cX[3]));
                nm2 = fmaxf(nm2, fmaxf(cY[0], cY[1]));
                nm3 = fmaxf(nm3, fmaxf(cY[2], cY[3]));
            } else {
                int cd0 = c0 + 2 * t4, cd1 = cd0 + 1;
                bool v0 = cd0 < A, v1 = cd1 < A;
                if (v0 && (cd0 < lo0 || cd0 >= hi0)) nm0 = fmaxf(nm0, cX[0]);
                if (v1 && (cd1 < lo0 || cd1 >= hi0)) nm0 = fmaxf(nm0, cX[1]);
                if (v0 && (cd0 < lo1 || cd0 >= hi1)) nm1 = fmaxf(nm1, cX[2]);
                if (v1 && (cd1 < lo1 || cd1 >= hi1)) nm1 = fmaxf(nm1, cX[3]);
                if (v0 && (cd0 < lo2 || cd0 >= hi2)) nm2 = fmaxf(nm2, cY[0]);
                if (v1 && (cd1 < lo2 || cd1 >= hi2)) nm2 = fmaxf(nm2, cY[1]);
                if (v0 && (cd0 < lo3 || cd0 >= hi3)) nm3 = fmaxf(nm3, cY[2]);
                if (v1 && (cd1 < lo3 || cd1 >= hi3)) nm3 = fmaxf(nm3, cY[3]);
            }
        }
    }

    nm0 = fmaxf(nm0, __shfl_xor_sync(0xffffffffu, nm0, 1));
    nm0 = fmaxf(nm0, __shfl_xor_sync(0xffffffffu, nm0, 2));
    nm1 = fmaxf(nm1, __shfl_xor_sync(0xffffffffu, nm1, 1));
    nm1 = fmaxf(nm1, __shfl_xor_sync(0xffffffffu, nm1, 2));
    nm2 = fmaxf(nm2, __shfl_xor_sync(0xffffffffu, nm2, 1));
    nm2 = fmaxf(nm2, __shfl_xor_sync(0xffffffffu, nm2, 2));
    nm3 = fmaxf(nm3, __shfl_xor_sync(0xffffffffu, nm3, 1));
    nm3 = fmaxf(nm3, __shfl_xor_sync(0xffffffffu, nm3, 2));
    if (t4 == 0) {
        if (r0 < A) g_negS[z][bNn + r0] = nm0;
        if (r1 < A) g_negS[z][bNn + r1] = nm1;
        if (r2 < A) g_negS[z][bNn + r2] = nm2;
        if (r3 < A) g_negS[z][bNn + r3] = nm3;
    }
}

// Launch #3: triplet loss + block reduction + fused finalize (+ counter reset)
__global__ void __launch_bounds__(256) k_loss(const float* __restrict__ posr,
                                              const void* __restrict__ gt,
                                              const void* __restrict__ fg,
                                              float* __restrict__ out, int out_size) {
    __shared__ int fl[2];
    detect_warp(gt, fg, threadIdx.x, fl);
    __syncthreads();
    int gt64 = fl[0], fg32 = fl[1];

    int i = blockIdx.x * blockDim.x + threadIdx.x;
    float per = 0.f;
    int cntv = 0;
    if (i < Bn * Nn && get_fg(fg, i, fg32)) {
        int b = i / Nn;
        int g = get_gt(gt, i, gt64);
        int cnt = g_cnt[b][g];
        int np = cnt - 1;
        int A = g_offs[b][Gn];
        if (np >= 1 && (A - cnt) > 0) {
            int slot = g_slot[i];
            int base = g_offs[b][g];
            int p = slot - base;

            float u = posr[i];
            int k = (int)floorf(u * (float)np);
            k = min(max(k, 0), np - 1);
            int sl = (k < p) ? k : k + 1;   // skip self in ordered group list
            int jslot = base + sl;

            const float4* ci = (const float4*)(g_mcoeff + ((size_t)b * Nn + slot) * Dn);
            const float4* cp = (const float4*)(g_mcoeff + ((size_t)b * Nn + jslot) * Dn);
            float ss = 0.f;
#pragma unroll
            for (int c = 0; c < 8; c++) {
                float4 u4 = ci[c], v4 = cp[c];
                float d0 = u4.x - v4.x, d1 = u4.y - v4.y;
                float d2 = u4.z - v4.z, d3 = u4.w - v4.w;
                ss = fmaf(d0, d0, ss); ss = fmaf(d1, d1, ss);
                ss = fmaf(d2, d2, ss); ss = fmaf(d3, d3, ss);
            }
            float pos_d = sqrtf(ss + EPSf);

            float s = g_negS[0][(size_t)b * Nn + slot];
#pragma unroll
            for (int zz = 1; zz < NSPLIT; zz++)
                s = fmaxf(s, g_negS[zz][(size_t)b * Nn + slot]);
            float nd2 = 2.0f - 2.0f * s;
            if (nd2 < 0.f) nd2 = 0.f;
            float neg_d = sqrtf(nd2 + EPSf);

            per = pos_d - neg_d + MARGINf;
            if (per < 0.f) per = 0.f;
            cntv = 1;
        }
    }
    double pv = (double)per;
#pragma unroll
    for (int o = 16; o > 0; o >>= 1) {
        pv   += __shfl_down_sync(0xffffffffu, pv, o);
        cntv += __shfl_down_sync(0xffffffffu, cntv, o);
    }
    __shared__ double sp[8];
    __shared__ int    sn[8];
    int w = threadIdx.x >> 5, l = threadIdx.x & 31;
    if (l == 0) { sp[w] = pv; sn[w] = cntv; }
    __syncthreads();
    if (w == 0) {
        double v = (l < 8) ? sp[l] : 0.0;
        int    n = (l < 8) ? sn[l] : 0;
#pragma unroll
        for (int o = 4; o > 0; o >>= 1) {
            v += __shfl_down_sync(0xffffffffu, v, o);
            n += __shfl_down_sync(0xffffffffu, n, o);
        }
        if (l == 0) {
            if (v != 0.0 || n != 0) {
                atomicAdd(&g_sum, v);
                atomicAdd(&g_num, n);
            }
            __threadfence();
            int prev = atomicAdd(&g_done, 1);
            if (prev == (int)gridDim.x - 1) {
                double fs = atomicAdd(&g_sum, 0.0);
                int    fn = atomicAdd(&g_num, 0);
                float val = (fn > 0) ? (float)(fs / (double)fn) : 0.0f;
                for (int o2 = 0; o2 < out_size; o2++) out[o2] = (o2 == 0) ? val : 0.0f;
                // reset all inter-launch state for the next graph replay
                g_sum = 0.0; g_num = 0; g_done = 0; g_arrive = 0;
            }
        }
    }
}

// ---------------- launch ----------------
extern "C" void kernel_launch(void* const* d_in, const int* in_sizes, int n_in,
                              void* d_out, int out_size) {
    const float* pred = (const float*)d_in[0];
    const float* posr = (const float*)d_in[1];
    const void*  gt   = (const void*)d_in[2];
    const void*  fg   = (const void*)d_in[3];
    float* out = (float*)d_out;

    dim3 gc(NCH, Bn);
    k_prep<<<gc, 128>>>(pred, gt, fg);
    dim3 gn(Nn / MT, Bn, NSPLIT);
    k_negmax<<<gn, 128, SMEM_NEG>>>();
    k_loss<<<(Bn * Nn + 255) / 256, 256>>>(posr, gt, fg, out, out_size);
}